// round 11
// baseline (speedup 1.0000x reference)
#include <cuda_runtime.h>
#include <cuda_fp16.h>
#include <cstdint>

// Problem: K=8192 rows, L=128 steps, D=64
#define NTH  512
#define NBLK 128
#define LT   128

// ---- smem byte offsets ----
#define HROW    144        // 64 fp16 = 128B data + 16B pad per row
#define HB_OFF  0          // 2 x 64 x 144 = 18432
#define HB_BUF  9216
#define X_OFF   18432      // 64 x 132 f32 = 33792
#define XS      132
#define HF_OFF  52224      // final h [64][66] f32 = 16896
#define CF_OFF  69120      // final c [64][66] f32 = 16896
#define VCB_OFF 86016      // float2[256] = 2048
#define RED_OFF 88064      // 2 x 1024 f32 = 8192
#define HS2_OFF 96256      // tail h_hat staging [64][66] f32 = 16896
#define SMEM_BYTES 113152
// tail overlays (recurrence-only regions reused)
#define WA_OFF  0
#define WF_OFF  X_OFF

typedef unsigned long long u64;

__device__ float g_Pfc[NBLK * 64];
__device__ float g_Phs[NBLK * 64];

__device__ __forceinline__ uint32_t smem_u32(const void* p) {
    uint32_t a;
    asm("{ .reg .u64 t; cvta.to.shared.u64 t, %1; cvt.u32.u64 %0, t; }" : "=r"(a) : "l"(p));
    return a;
}
__device__ __forceinline__ void ldmx4(uint32_t* r, uint32_t addr) {
    asm volatile("ldmatrix.sync.aligned.m8n8.x4.shared.b16 {%0,%1,%2,%3}, [%4];"
                 : "=r"(r[0]), "=r"(r[1]), "=r"(r[2]), "=r"(r[3]) : "r"(addr));
}
// fp16-accumulator HMMA: D/C are 2 regs (half2 x2)
__device__ __forceinline__ void mma16816h(uint32_t* d, const uint32_t* a, const uint32_t* b) {
    asm volatile("mma.sync.aligned.m16n8k16.row.col.f16.f16.f16.f16 "
                 "{%0,%1}, {%2,%3,%4,%5}, {%6,%7}, {%0,%1};"
                 : "+r"(d[0]), "+r"(d[1])
                 : "r"(a[0]), "r"(a[1]), "r"(a[2]), "r"(a[3]), "r"(b[0]), "r"(b[1]));
}
__device__ __forceinline__ uint32_t pkh2(__half lo, __half hi) {
    return ((uint32_t)__half_as_ushort(hi) << 16) | __half_as_ushort(lo);
}
// fast fp32 tanh (1 MUFU)
__device__ __forceinline__ float tanh_a(float x) {
    float r;
    asm("tanh.approx.f32 %0, %1;" : "=f"(r) : "f"(x));
    return r;
}
// accurate versions for tail / finale
__device__ __forceinline__ float sigf(float x)   { return 1.0f / (1.0f + __expf(-x)); }
__device__ __forceinline__ float tanh_f(float x) { float e = __expf(2.0f * x); return 1.0f - 2.0f / (e + 1.0f); }

#define BARW(id) asm volatile("bar.sync %0, 256;" :: "r"(id) : "memory")

__global__ __launch_bounds__(NTH, 1)
void lstm_main(const float* __restrict__ x,
               const float* __restrict__ W_num, const float* __restrict__ b_num,
               const float* __restrict__ W_ih,  const float* __restrict__ W_hh,
               const float* __restrict__ b_ih,  const float* __restrict__ b_hh,
               const float* __restrict__ W_aout, const float* __restrict__ b_aout,
               const float* __restrict__ W_fh,   const float* __restrict__ b_fh)
{
    extern __shared__ char smem[];
    const uint32_t sb = smem_u32(smem);

    float*  x_s   = (float*)(smem + X_OFF);
    float*  hf_s  = (float*)(smem + HF_OFF);
    float*  cf_s  = (float*)(smem + CF_OFF);
    float2* vcb_s = (float2*)(smem + VCB_OFF);
    float*  red   = (float*)(smem + RED_OFF);

    const int tid  = threadIdx.x;
    const int l    = tid & 31;
    const int wid  = tid >> 5;
    const int wm   = wid >> 3;          // row-group: rows wm*32 .. +31
    const int wn   = wid & 7;           // unit-group: units wn*8 .. +7
    const int c    = l & 3;
    const int quad = l >> 2;
    const int u0   = 8 * wn + 2 * c;    // this thread's unit pair u0, u0+1
    const int barid = 1 + wm;           // per-row-group named barrier

    // ---- zero h buffer 0 (h(0)=0) ----
    for (int i = tid; i < HB_BUF / 4; i += NTH) ((uint32_t*)(smem + HB_OFF))[i] = 0u;

    // ---- stage x rows (padded stride, bank-spread) ----
    {
        const float* xg = x + (size_t)blockIdx.x * (64 * LT);
        for (int i = tid; i < 64 * LT; i += NTH) x_s[(i >> 7) * XS + (i & 127)] = xg[i];
    }

    // ---- rank-1 input precompute, stored at remapped gate index m ----
    // orig gate g = q*64+u (q: 0=i,1=f,2=g,3=o)
    // m = (q>>1)*128 + (u>>3)*16 + (u&1)*8 + ((u>>1)&3)*2 + (q&1)
    // i/f/o gates pre-halved so sig(x) = 0.5*tanh(x_halved)+0.5
    if (tid < 256) {
        int g = tid;
        const float* wr = W_ih + g * 128;   // (256,128); first 64 cols used
        float v = 0.0f, cb = 0.0f;
        #pragma unroll 8
        for (int j = 0; j < 64; ++j) {
            float ww = wr[j];
            v  = fmaf(ww, W_num[j], v);
            cb = fmaf(ww, b_num[j], cb);
        }
        int q = g >> 6, u = g & 63;
        float sc = (q == 2) ? 1.0f : 0.5f;
        int m = (q >> 1) * 128 + (u >> 3) * 16 + (u & 1) * 8 + ((u >> 1) & 3) * 2 + (q & 1);
        vcb_s[m] = make_float2(v * sc, (cb + b_ih[g] + b_hh[g]) * sc);
    }

    // ---- W fragments (fp16, i/f/o pre-halved) in registers ----
    uint32_t Bh[4][4][2];
    #pragma unroll
    for (int nt = 0; nt < 4; ++nt) {
        int u = 8 * wn + 2 * (quad >> 1) + (nt & 1);
        int q = (nt >> 1) * 2 + (quad & 1);
        float sc = (q == 2) ? 1.0f : 0.5f;
        const float* wr = W_hh + (q * 64 + u) * 64;
        #pragma unroll
        for (int kk = 0; kk < 4; ++kk) {
            int j0 = kk * 16 + 2 * c;
            Bh[nt][kk][0] = pkh2(__float2half(wr[j0] * sc),     __float2half(wr[j0 + 1] * sc));
            Bh[nt][kk][1] = pkh2(__float2half(wr[j0 + 8] * sc), __float2half(wr[j0 + 9] * sc));
        }
    }
    __syncthreads();

    // hoist step-invariant gate constants into registers
    float2 P0[4], P1[4];
    #pragma unroll
    for (int nt = 0; nt < 4; ++nt) {
        int mb = (nt >> 1) * 128 + wn * 16 + (nt & 1) * 8 + 2 * c;
        P0[nt] = vcb_s[mb];
        P1[nt] = vcb_s[mb + 1];
    }

    // c-state in fp32 (prevents accumulation drift)
    float cst[2][2][2];   // [mt][rr][z]
    #pragma unroll
    for (int mt = 0; mt < 2; ++mt)
        #pragma unroll
        for (int rr = 0; rr < 2; ++rr) { cst[mt][rr][0] = 0.0f; cst[mt][rr][1] = 0.0f; }

    const uint32_t abase = sb + HB_OFF + (wm * 32 + (l & 15)) * HROW + (l >> 4) * 16;

    // ================= recurrence: 128 sequential steps =================
    for (int t = 0; t < LT; ++t) {
        // --- init D (fp16x2 accumulators) with rank-1 x-term + fused bias ---
        uint32_t D[2][4][2];
        float xv[2][2];
        #pragma unroll
        for (int mt = 0; mt < 2; ++mt) {
            int ra = wm * 32 + mt * 16 + quad;
            xv[mt][0] = x_s[ra * XS + t];
            xv[mt][1] = x_s[(ra + 8) * XS + t];
        }
        #pragma unroll
        for (int nt = 0; nt < 4; ++nt) {
            float2 p0 = P0[nt], p1 = P1[nt];
            #pragma unroll
            for (int mt = 0; mt < 2; ++mt) {
                __half2 d0 = __floats2half2_rn(fmaf(xv[mt][0], p0.x, p0.y),
                                               fmaf(xv[mt][0], p1.x, p1.y));
                __half2 d1 = __floats2half2_rn(fmaf(xv[mt][1], p0.x, p0.y),
                                               fmaf(xv[mt][1], p1.x, p1.y));
                D[mt][nt][0] = *(uint32_t*)&d0;
                D[mt][nt][1] = *(uint32_t*)&d1;
            }
        }

        // --- D += h @ W^T : fp16 mma, fp16 accumulate ---
        const uint32_t ab = abase + (t & 1) * HB_BUF;
        #pragma unroll
        for (int kk = 0; kk < 4; ++kk) {
            uint32_t Ah0[4], Ah1[4];
            ldmx4(Ah0, ab + kk * 32);
            ldmx4(Ah1, ab + 16 * HROW + kk * 32);
            #pragma unroll
            for (int nt = 0; nt < 4; ++nt) {
                mma16816h(D[0][nt], Ah0, Bh[nt][kk]);
                mma16816h(D[1][nt], Ah1, Bh[nt][kk]);
            }
        }

        // --- epilogue: fp32 activations + fp32 c-state ---
        char* hnext = smem + HB_OFF + ((t + 1) & 1) * HB_BUF;
        #pragma unroll
        for (int mt = 0; mt < 2; ++mt)
            #pragma unroll
            for (int rr = 0; rr < 2; ++rr) {
                int row = wm * 32 + mt * 16 + quad + 8 * rr;
                float hz[2];
                #pragma unroll
                for (int z = 0; z < 2; ++z) {
                    __half2 dif = *(__half2*)&D[mt][z][rr];       // (i, f), pre-halved
                    __half2 dgo = *(__half2*)&D[mt][2 + z][rr];   // (g, o), o pre-halved
                    float gi = __low2float(dif),  gf = __high2float(dif);
                    float gg = __low2float(dgo),  go = __high2float(dgo);
                    float si = fmaf(tanh_a(gi), 0.5f, 0.5f);
                    float sf = fmaf(tanh_a(gf), 0.5f, 0.5f);
                    float so = fmaf(tanh_a(go), 0.5f, 0.5f);
                    float cn = sf * cst[mt][rr][z] + si * tanh_a(gg);
                    cst[mt][rr][z] = cn;
                    hz[z] = so * tanh_a(cn);
                    if (t == LT - 1) {
                        hf_s[row * 66 + u0 + z] = hz[z];
                        cf_s[row * 66 + u0 + z] = cn;
                    }
                }
                if (t < LT - 1) {
                    __half2 hp = __floats2half2_rn(hz[0], hz[1]);
                    *(uint32_t*)(hnext + row * HROW + 2 * u0) = *(uint32_t*)&hp;
                }
            }
        BARW(barid);
    }
    __syncthreads();   // join row-groups before tail overlays

    // ================= tail =================
    float* wa  = (float*)(smem + WA_OFF);    // [j*66+u]
    float* wf  = (float*)(smem + WF_OFF);
    float* hs2 = (float*)(smem + HS2_OFF);   // h_hat staging [r][66]
    for (int idx = tid; idx < 4096; idx += NTH) {
        int u = idx >> 6, j = idx & 63;
        wa[j * 66 + u] = W_aout[idx];
        wf[j * 66 + u] = W_fh[idx];
    }
    __syncthreads();

    const int tw = wid;            // 16 warps
    const int r0 = tw * 4;         // rows r0..r0+3
    const int tu = 2 * l;          // units tu, tu+1

    // h_hat = h @ W_aout^T + b_aout
    float hh2[2][4];
    {
        float b0 = b_aout[tu], b1 = b_aout[tu + 1];
        #pragma unroll
        for (int rr = 0; rr < 4; ++rr) { hh2[0][rr] = b0; hh2[1][rr] = b1; }
        #pragma unroll 8
        for (int j = 0; j < 64; ++j) {
            float w0 = wa[j * 66 + tu], w1 = wa[j * 66 + tu + 1];
            #pragma unroll
            for (int rr = 0; rr < 4; ++rr) {
                float hj = hf_s[(r0 + rr) * 66 + j];
                hh2[0][rr] = fmaf(hj, w0, hh2[0][rr]);
                hh2[1][rr] = fmaf(hj, w1, hh2[1][rr]);
            }
        }
        #pragma unroll
        for (int rr = 0; rr < 4; ++rr) {
            hs2[(r0 + rr) * 66 + tu]     = hh2[0][rr];
            hs2[(r0 + rr) * 66 + tu + 1] = hh2[1][rr];
        }
    }
    __syncthreads();

    // f = h_hat @ W_fh^T + b_fh ; partial sums
    float fv2[2][4];
    {
        float b0 = b_fh[tu], b1 = b_fh[tu + 1];
        #pragma unroll
        for (int rr = 0; rr < 4; ++rr) { fv2[0][rr] = b0; fv2[1][rr] = b1; }
        #pragma unroll 8
        for (int j = 0; j < 64; ++j) {
            float w0 = wf[j * 66 + tu], w1 = wf[j * 66 + tu + 1];
            #pragma unroll
            for (int rr = 0; rr < 4; ++rr) {
                float hj = hs2[(r0 + rr) * 66 + j];
                fv2[0][rr] = fmaf(hj, w0, fv2[0][rr]);
                fv2[1][rr] = fmaf(hj, w1, fv2[1][rr]);
            }
        }
    }

    float fc0 = 0.0f, fc1 = 0.0f, hs0 = 0.0f, hs1 = 0.0f;
    #pragma unroll
    for (int rr = 0; rr < 4; ++rr) {
        fc0 += sigf(fv2[0][rr]) * cf_s[(r0 + rr) * 66 + tu];
        fc1 += sigf(fv2[1][rr]) * cf_s[(r0 + rr) * 66 + tu + 1];
        hs0 += hh2[0][rr];
        hs1 += hh2[1][rr];
    }
    red[tw * 64 + tu]            = fc0;
    red[tw * 64 + tu + 1]        = fc1;
    red[1024 + tw * 64 + tu]     = hs0;
    red[1024 + tw * 64 + tu + 1] = hs1;
    __syncthreads();

    if (tid < 64) {
        float a = 0.0f, b = 0.0f;
        #pragma unroll
        for (int g = 0; g < 16; ++g) {
            a += red[g * 64 + tid];
            b += red[1024 + g * 64 + tid];
        }
        g_Pfc[blockIdx.x * 64 + tid] = a;
        g_Phs[blockIdx.x * 64 + tid] = b;
    }
}

// ================= finale: parallel reduce + object-cell head (1024 thr) =================
__global__ __launch_bounds__(1024, 1)
void lstm_final(const float* __restrict__ W_iouh, const float* __restrict__ b_iouh,
                const float* __restrict__ W_oout, const float* __restrict__ b_oout,
                float* __restrict__ out)
{
    __shared__ float s_fc[16][64];
    __shared__ float s_hs[16][64];
    __shared__ float hsb[64];
    __shared__ float fcb[64];
    __shared__ float s_g[192][4];
    __shared__ float iouv[192];
    __shared__ float hob[64];
    __shared__ float s_o[64][16];

    const int tid = threadIdx.x;   // 1024
    const int q = tid >> 6, u = tid & 63;

    // phase 1: reduce per-block partials (128 blocks -> 16 -> 1)
    float fc = 0.0f, hs = 0.0f;
    #pragma unroll
    for (int b = q; b < NBLK; b += 16) {
        fc += g_Pfc[b * 64 + u];
        hs += g_Phs[b * 64 + u];
    }
    s_fc[q][u] = fc;
    s_hs[q][u] = hs;
    __syncthreads();
    if (tid < 64) {
        float a = 0.0f, b = 0.0f;
        #pragma unroll
        for (int k = 0; k < 16; ++k) { a += s_fc[k][tid]; b += s_hs[k][tid]; }
        fcb[tid] = a;
        hsb[tid] = b;
    }
    __syncthreads();

    // phase 2: iou = hsb @ W_iouh^T + b_iouh  (192 outputs x 4 K-chunks)
    if (tid < 768) {
        int g = tid >> 2, ch = tid & 3;
        const float* wr = W_iouh + g * 64 + ch * 16;
        const float* hp = hsb + ch * 16;
        float s = 0.0f;
        #pragma unroll
        for (int j = 0; j < 16; ++j) s = fmaf(hp[j], wr[j], s);
        s_g[g][ch] = s;
    }
    __syncthreads();
    if (tid < 192)
        iouv[tid] = s_g[tid][0] + s_g[tid][1] + s_g[tid][2] + s_g[tid][3] + b_iouh[tid];
    __syncthreads();

    // phase 3: object cell
    if (tid < 64) {
        float c_obj = sigf(iouv[tid]) * tanh_f(iouv[128 + tid]) + fcb[tid];
        float h_obj = sigf(iouv[64 + tid]) * tanh_f(c_obj);
        hob[tid] = h_obj;
        out[64 + tid] = c_obj;
    }
    __syncthreads();

    // phase 4: out[0:64] = hob @ W_oout^T + b_oout (64 outputs x 16 K-chunks)
    {
        int uo = tid >> 4, ch = tid & 15;
        const float* wr = W_oout + uo * 64 + ch * 4;
        const float* hp = hob + ch * 4;
        float s = 0.0f;
        #pragma unroll
        for (int j = 0; j < 4; ++j) s = fmaf(hp[j], wr[j], s);
        s_o[uo][ch] = s;
    }
    __syncthreads();
    if (tid < 64) {
        float s = b_oout[tid];
        #pragma unroll
        for (int k = 0; k < 16; ++k) s += s_o[tid][k];
        out[tid] = s;
    }
}

extern "C" void kernel_launch(void* const* d_in, const int* in_sizes, int n_in,
                              void* d_out, int out_size)
{
    const float* x      = (const float*)d_in[0];
    const float* W_num  = (const float*)d_in[1];
    const float* b_num  = (const float*)d_in[2];
    const float* W_ih   = (const float*)d_in[3];
    const float* W_hh   = (const float*)d_in[4];
    const float* b_ih   = (const float*)d_in[5];
    const float* b_hh   = (const float*)d_in[6];
    const float* W_aout = (const float*)d_in[7];
    const float* b_aout = (const float*)d_in[8];
    const float* W_fh   = (const float*)d_in[9];
    const float* b_fh   = (const float*)d_in[10];
    const float* W_iouh = (const float*)d_in[11];
    const float* b_iouh = (const float*)d_in[12];
    const float* W_oout = (const float*)d_in[13];
    const float* b_oout = (const float*)d_in[14];

    (void)in_sizes; (void)n_in; (void)out_size;

    cudaFuncSetAttribute(lstm_main, cudaFuncAttributeMaxDynamicSharedMemorySize, SMEM_BYTES);

    lstm_main<<<NBLK, NTH, SMEM_BYTES>>>(x, W_num, b_num, W_ih, W_hh, b_ih, b_hh,
                                         W_aout, b_aout, W_fh, b_fh);
    lstm_final<<<1, 1024>>>(W_iouh, b_iouh, W_oout, b_oout, (float*)d_out);
}

// round 12
// speedup vs baseline: 1.0158x; 1.0158x over previous
#include <cuda_runtime.h>
#include <cuda_fp16.h>
#include <cstdint>

// Problem: K=8192 rows, L=128 steps, D=64
#define NTH  512
#define NBLK 128
#define LT   128

// ---- smem byte offsets ----
#define HROW    144        // 64 fp16 = 128B data + 16B pad per row
#define HB_OFF  0          // 2 x 64 x 144 = 18432
#define HB_BUF  9216
#define X_OFF   18432      // 64 x 132 f32 = 33792
#define XS      132
#define HF_OFF  52224      // final h [64][66] f32 = 16896
#define CF_OFF  69120      // final c [64][66] f32 = 16896
#define VCB_OFF 86016      // float2[256] = 2048
#define RED_OFF 88064      // 2 x 1024 f32 = 8192
#define HS2_OFF 96256      // tail h_hat staging [64][66] f32 = 16896
#define SMEM_BYTES 113152
// tail overlays (recurrence-only regions reused)
#define WA_OFF  0
#define WF_OFF  X_OFF

typedef unsigned long long u64;

__device__ float g_Pfc[NBLK * 64];
__device__ float g_Phs[NBLK * 64];
__device__ unsigned int g_ctr = 0;

__device__ __forceinline__ uint32_t smem_u32(const void* p) {
    uint32_t a;
    asm("{ .reg .u64 t; cvta.to.shared.u64 t, %1; cvt.u32.u64 %0, t; }" : "=r"(a) : "l"(p));
    return a;
}
__device__ __forceinline__ void ldmx4(uint32_t* r, uint32_t addr) {
    asm volatile("ldmatrix.sync.aligned.m8n8.x4.shared.b16 {%0,%1,%2,%3}, [%4];"
                 : "=r"(r[0]), "=r"(r[1]), "=r"(r[2]), "=r"(r[3]) : "r"(addr));
}
__device__ __forceinline__ void mma16816(float* d, const uint32_t* a, const uint32_t* b) {
    asm volatile("mma.sync.aligned.m16n8k16.row.col.f32.f16.f16.f32 "
                 "{%0,%1,%2,%3}, {%4,%5,%6,%7}, {%8,%9}, {%0,%1,%2,%3};"
                 : "+f"(d[0]), "+f"(d[1]), "+f"(d[2]), "+f"(d[3])
                 : "r"(a[0]), "r"(a[1]), "r"(a[2]), "r"(a[3]), "r"(b[0]), "r"(b[1]));
}
__device__ __forceinline__ uint32_t pkh2(__half lo, __half hi) {
    return ((uint32_t)__half_as_ushort(hi) << 16) | __half_as_ushort(lo);
}
// packed fp16x2 tanh (1 MUFU for two lanes)
__device__ __forceinline__ __half2 tanh_h2(__half2 x) {
    uint32_t xi = *(uint32_t*)&x, ri;
    asm("tanh.approx.f16x2 %0, %1;" : "=r"(ri) : "r"(xi));
    return *(__half2*)&ri;
}
// fast fp32 tanh (1 MUFU)
__device__ __forceinline__ float tanh_a(float x) {
    float r;
    asm("tanh.approx.f32 %0, %1;" : "=f"(r) : "f"(x));
    return r;
}
// accurate versions for tail / finale
__device__ __forceinline__ float sigf(float x)   { return 1.0f / (1.0f + __expf(-x)); }
__device__ __forceinline__ float tanh_f(float x) { float e = __expf(2.0f * x); return 1.0f - 2.0f / (e + 1.0f); }

#define BARW(id) asm volatile("bar.sync %0, 256;" :: "r"(id) : "memory")

__global__ __launch_bounds__(NTH, 1)
void lstm_main(const float* __restrict__ x,
               const float* __restrict__ W_num, const float* __restrict__ b_num,
               const float* __restrict__ W_ih,  const float* __restrict__ W_hh,
               const float* __restrict__ b_ih,  const float* __restrict__ b_hh,
               const float* __restrict__ W_aout, const float* __restrict__ b_aout,
               const float* __restrict__ W_fh,   const float* __restrict__ b_fh,
               const float* __restrict__ W_iouh, const float* __restrict__ b_iouh,
               const float* __restrict__ W_oout, const float* __restrict__ b_oout,
               float* __restrict__ out)
{
    extern __shared__ char smem[];
    const uint32_t sb = smem_u32(smem);

    float*  x_s   = (float*)(smem + X_OFF);
    float*  hf_s  = (float*)(smem + HF_OFF);
    float*  cf_s  = (float*)(smem + CF_OFF);
    float2* vcb_s = (float2*)(smem + VCB_OFF);
    float*  red   = (float*)(smem + RED_OFF);

    const int tid  = threadIdx.x;
    const int l    = tid & 31;
    const int wid  = tid >> 5;
    const int wm   = wid >> 3;          // row-group: rows wm*32 .. +31
    const int wn   = wid & 7;           // unit-group: units wn*8 .. +7
    const int c    = l & 3;
    const int quad = l >> 2;
    const int u0   = 8 * wn + 2 * c;    // this thread's unit pair u0, u0+1
    const int barid = 1 + wm;           // per-row-group named barrier

    // ---- zero h buffer 0 (h(0)=0) ----
    for (int i = tid; i < HB_BUF / 4; i += NTH) ((uint32_t*)(smem + HB_OFF))[i] = 0u;

    // ---- stage x rows (padded stride, bank-spread) ----
    {
        const float* xg = x + (size_t)blockIdx.x * (64 * LT);
        for (int i = tid; i < 64 * LT; i += NTH) x_s[(i >> 7) * XS + (i & 127)] = xg[i];
    }

    // ---- rank-1 input precompute, stored at remapped gate index m ----
    // orig gate g = q*64+u (q: 0=i,1=f,2=g,3=o)
    // m = (q>>1)*128 + (u>>3)*16 + (u&1)*8 + ((u>>1)&3)*2 + (q&1)
    // i/f/o gates pre-halved so sig(x) = 0.5*tanh(x_halved)+0.5
    if (tid < 256) {
        int g = tid;
        const float* wr = W_ih + g * 128;   // (256,128); first 64 cols used
        float v = 0.0f, cb = 0.0f;
        #pragma unroll 8
        for (int j = 0; j < 64; ++j) {
            float ww = wr[j];
            v  = fmaf(ww, W_num[j], v);
            cb = fmaf(ww, b_num[j], cb);
        }
        int q = g >> 6, u = g & 63;
        float sc = (q == 2) ? 1.0f : 0.5f;
        int m = (q >> 1) * 128 + (u >> 3) * 16 + (u & 1) * 8 + ((u >> 1) & 3) * 2 + (q & 1);
        vcb_s[m] = make_float2(v * sc, (cb + b_ih[g] + b_hh[g]) * sc);
    }

    // ---- W fragments (fp16, i/f/o pre-halved) in registers ----
    uint32_t Bh[4][4][2];
    #pragma unroll
    for (int nt = 0; nt < 4; ++nt) {
        int u = 8 * wn + 2 * (quad >> 1) + (nt & 1);
        int q = (nt >> 1) * 2 + (quad & 1);
        float sc = (q == 2) ? 1.0f : 0.5f;
        const float* wr = W_hh + (q * 64 + u) * 64;
        #pragma unroll
        for (int kk = 0; kk < 4; ++kk) {
            int j0 = kk * 16 + 2 * c;
            Bh[nt][kk][0] = pkh2(__float2half(wr[j0] * sc),     __float2half(wr[j0 + 1] * sc));
            Bh[nt][kk][1] = pkh2(__float2half(wr[j0 + 8] * sc), __float2half(wr[j0 + 9] * sc));
        }
    }
    __syncthreads();

    // hoist step-invariant gate constants into registers
    float2 P0[4], P1[4];
    #pragma unroll
    for (int nt = 0; nt < 4; ++nt) {
        int mb = (nt >> 1) * 128 + wn * 16 + (nt & 1) * 8 + 2 * c;
        P0[nt] = vcb_s[mb];
        P1[nt] = vcb_s[mb + 1];
    }

    // c-state in fp32 (prevents accumulation drift)
    float cst[2][2][2];   // [mt][rr][z]
    #pragma unroll
    for (int mt = 0; mt < 2; ++mt)
        #pragma unroll
        for (int rr = 0; rr < 2; ++rr) { cst[mt][rr][0] = 0.0f; cst[mt][rr][1] = 0.0f; }

    const uint32_t abase = sb + HB_OFF + (wm * 32 + (l & 15)) * HROW + (l >> 4) * 16;

    // ================= recurrence: 128 sequential steps =================
    for (int t = 0; t < LT; ++t) {
        // --- init D with rank-1 x-term + fused bias ---
        float D[2][4][4];
        float xv[2][2];
        #pragma unroll
        for (int mt = 0; mt < 2; ++mt) {
            int ra = wm * 32 + mt * 16 + quad;
            xv[mt][0] = x_s[ra * XS + t];
            xv[mt][1] = x_s[(ra + 8) * XS + t];
        }
        #pragma unroll
        for (int nt = 0; nt < 4; ++nt) {
            float2 p0 = P0[nt], p1 = P1[nt];
            #pragma unroll
            for (int mt = 0; mt < 2; ++mt) {
                D[mt][nt][0] = fmaf(xv[mt][0], p0.x, p0.y);
                D[mt][nt][1] = fmaf(xv[mt][0], p1.x, p1.y);
                D[mt][nt][2] = fmaf(xv[mt][1], p0.x, p0.y);
                D[mt][nt][3] = fmaf(xv[mt][1], p1.x, p1.y);
            }
        }

        // --- D += h @ W^T : fp16 mma, fp32 accumulate ---
        const uint32_t ab = abase + (t & 1) * HB_BUF;
        #pragma unroll
        for (int kk = 0; kk < 4; ++kk) {
            uint32_t Ah0[4], Ah1[4];
            ldmx4(Ah0, ab + kk * 32);
            ldmx4(Ah1, ab + 16 * HROW + kk * 32);
            #pragma unroll
            for (int nt = 0; nt < 4; ++nt) {
                mma16816(D[0][nt], Ah0, Bh[nt][kk]);
                mma16816(D[1][nt], Ah1, Bh[nt][kk]);
            }
        }

        // --- epilogue: packed f16x2 sigmoids, fp32 g/c tanh, fp32 c-state ---
        char* hnext = smem + HB_OFF + ((t + 1) & 1) * HB_BUF;
        #pragma unroll
        for (int mt = 0; mt < 2; ++mt)
            #pragma unroll
            for (int rr = 0; rr < 2; ++rr) {
                int row = wm * 32 + mt * 16 + quad + 8 * rr;
                // pre-halved i/f/o packed over z (z = unit index within pair)
                __half2 ti2 = tanh_h2(__floats2half2_rn(D[mt][0][2 * rr],     D[mt][1][2 * rr]));
                __half2 tf2 = tanh_h2(__floats2half2_rn(D[mt][0][2 * rr + 1], D[mt][1][2 * rr + 1]));
                __half2 to2 = tanh_h2(__floats2half2_rn(D[mt][2][2 * rr + 1], D[mt][3][2 * rr + 1]));
                float tg0 = tanh_a(D[mt][2][2 * rr]);
                float tg1 = tanh_a(D[mt][3][2 * rr]);
                float si0 = fmaf(__low2float(ti2),  0.5f, 0.5f);
                float si1 = fmaf(__high2float(ti2), 0.5f, 0.5f);
                float sf0 = fmaf(__low2float(tf2),  0.5f, 0.5f);
                float sf1 = fmaf(__high2float(tf2), 0.5f, 0.5f);
                float so0 = fmaf(__low2float(to2),  0.5f, 0.5f);
                float so1 = fmaf(__high2float(to2), 0.5f, 0.5f);
                float cn0 = sf0 * cst[mt][rr][0] + si0 * tg0;
                float cn1 = sf1 * cst[mt][rr][1] + si1 * tg1;
                cst[mt][rr][0] = cn0;
                cst[mt][rr][1] = cn1;
                float h0 = so0 * tanh_a(cn0);
                float h1 = so1 * tanh_a(cn1);
                if (t < LT - 1) {
                    __half2 hp = __floats2half2_rn(h0, h1);
                    *(uint32_t*)(hnext + row * HROW + 2 * u0) = *(uint32_t*)&hp;
                } else {
                    hf_s[row * 66 + u0]     = h0;
                    hf_s[row * 66 + u0 + 1] = h1;
                    cf_s[row * 66 + u0]     = cn0;
                    cf_s[row * 66 + u0 + 1] = cn1;
                }
            }
        BARW(barid);
    }
    __syncthreads();   // join row-groups before tail overlays

    // ================= tail =================
    float* wa  = (float*)(smem + WA_OFF);    // [j*66+u]
    float* wf  = (float*)(smem + WF_OFF);
    float* hs2 = (float*)(smem + HS2_OFF);   // h_hat staging [r][66]
    for (int idx = tid; idx < 4096; idx += NTH) {
        int u = idx >> 6, j = idx & 63;
        wa[j * 66 + u] = W_aout[idx];
        wf[j * 66 + u] = W_fh[idx];
    }
    __syncthreads();

    const int tw = wid;            // 16 warps
    const int r0 = tw * 4;         // rows r0..r0+3
    const int tu = 2 * l;          // units tu, tu+1

    // h_hat = h @ W_aout^T + b_aout
    float hh2[2][4];
    {
        float b0 = b_aout[tu], b1 = b_aout[tu + 1];
        #pragma unroll
        for (int rr = 0; rr < 4; ++rr) { hh2[0][rr] = b0; hh2[1][rr] = b1; }
        #pragma unroll 8
        for (int j = 0; j < 64; ++j) {
            float w0 = wa[j * 66 + tu], w1 = wa[j * 66 + tu + 1];
            #pragma unroll
            for (int rr = 0; rr < 4; ++rr) {
                float hj = hf_s[(r0 + rr) * 66 + j];
                hh2[0][rr] = fmaf(hj, w0, hh2[0][rr]);
                hh2[1][rr] = fmaf(hj, w1, hh2[1][rr]);
            }
        }
        #pragma unroll
        for (int rr = 0; rr < 4; ++rr) {
            hs2[(r0 + rr) * 66 + tu]     = hh2[0][rr];
            hs2[(r0 + rr) * 66 + tu + 1] = hh2[1][rr];
        }
    }
    __syncthreads();

    // f = h_hat @ W_fh^T + b_fh ; partial sums
    float fv2[2][4];
    {
        float b0 = b_fh[tu], b1 = b_fh[tu + 1];
        #pragma unroll
        for (int rr = 0; rr < 4; ++rr) { fv2[0][rr] = b0; fv2[1][rr] = b1; }
        #pragma unroll 8
        for (int j = 0; j < 64; ++j) {
            float w0 = wf[j * 66 + tu], w1 = wf[j * 66 + tu + 1];
            #pragma unroll
            for (int rr = 0; rr < 4; ++rr) {
                float hj = hs2[(r0 + rr) * 66 + j];
                fv2[0][rr] = fmaf(hj, w0, fv2[0][rr]);
                fv2[1][rr] = fmaf(hj, w1, fv2[1][rr]);
            }
        }
    }

    float fc0 = 0.0f, fc1 = 0.0f, hs0 = 0.0f, hs1 = 0.0f;
    #pragma unroll
    for (int rr = 0; rr < 4; ++rr) {
        fc0 += sigf(fv2[0][rr]) * cf_s[(r0 + rr) * 66 + tu];
        fc1 += sigf(fv2[1][rr]) * cf_s[(r0 + rr) * 66 + tu + 1];
        hs0 += hh2[0][rr];
        hs1 += hh2[1][rr];
    }
    red[tw * 64 + tu]            = fc0;
    red[tw * 64 + tu + 1]        = fc1;
    red[1024 + tw * 64 + tu]     = hs0;
    red[1024 + tw * 64 + tu + 1] = hs1;
    __syncthreads();

    if (tid < 64) {
        float a = 0.0f, b = 0.0f;
        #pragma unroll
        for (int g = 0; g < 16; ++g) {
            a += red[g * 64 + tid];
            b += red[1024 + g * 64 + tid];
        }
        g_Pfc[blockIdx.x * 64 + tid] = a;
        g_Phs[blockIdx.x * 64 + tid] = b;
    }

    // ================= fused finale: last CTA reduces + runs the head =================
    __shared__ unsigned int s_win;
    __threadfence();                      // release partials
    __syncthreads();
    if (tid == 0) {
        unsigned int v = atomicAdd(&g_ctr, 1u);
        s_win = (v == NBLK - 1) ? 1u : 0u;
    }
    __syncthreads();
    if (!s_win) return;

    if (tid == 0) g_ctr = 0;              // reset for next graph replay
    __threadfence();                      // acquire: partials of all CTAs now visible

    __shared__ float f_fc[8][64], f_hs[8][64], f_hsb[64], f_fcb[64];
    __shared__ float f_g[192][2], f_iou[192], f_hob[64], f_o[64][8];

    // phase 1: reduce per-block partials (128 -> 8 -> 1)
    {
        int q = tid >> 6, u = tid & 63;
        float fc = 0.0f, hs = 0.0f;
        #pragma unroll
        for (int b = q; b < NBLK; b += 8) {
            fc += g_Pfc[b * 64 + u];
            hs += g_Phs[b * 64 + u];
        }
        f_fc[q][u] = fc;
        f_hs[q][u] = hs;
    }
    __syncthreads();
    if (tid < 64) {
        float a = 0.0f, b = 0.0f;
        #pragma unroll
        for (int k = 0; k < 8; ++k) { a += f_fc[k][tid]; b += f_hs[k][tid]; }
        f_fcb[tid] = a;
        f_hsb[tid] = b;
    }
    __syncthreads();

    // phase 2: iou = hsb @ W_iouh^T + b_iouh (192 outputs x 2 K-chunks)
    if (tid < 384) {
        int g = tid >> 1, ch = tid & 1;
        const float* wr = W_iouh + g * 64 + ch * 32;
        const float* hp = f_hsb + ch * 32;
        float s = 0.0f;
        #pragma unroll 8
        for (int j = 0; j < 32; ++j) s = fmaf(hp[j], wr[j], s);
        f_g[g][ch] = s;
    }
    __syncthreads();
    if (tid < 192) f_iou[tid] = f_g[tid][0] + f_g[tid][1] + b_iouh[tid];
    __syncthreads();

    // phase 3: object cell (accurate activations)
    if (tid < 64) {
        float c_obj = sigf(f_iou[tid]) * tanh_f(f_iou[128 + tid]) + f_fcb[tid];
        float h_obj = sigf(f_iou[64 + tid]) * tanh_f(c_obj);
        f_hob[tid] = h_obj;
        out[64 + tid] = c_obj;
    }
    __syncthreads();

    // phase 4: out[0:64] = hob @ W_oout^T + b_oout (64 outputs x 8 K-chunks)
    {
        int uo = tid >> 3, ch = tid & 7;
        const float* wr = W_oout + uo * 64 + ch * 8;
        const float* hp = f_hob + ch * 8;
        float s = 0.0f;
        #pragma unroll
        for (int j = 0; j < 8; ++j) s = fmaf(hp[j], wr[j], s);
        f_o[uo][ch] = s;
    }
    __syncthreads();
    if (tid < 64) {
        float s = b_oout[tid];
        #pragma unroll
        for (int k = 0; k < 8; ++k) s += f_o[tid][k];
        out[tid] = s;
    }
}

extern "C" void kernel_launch(void* const* d_in, const int* in_sizes, int n_in,
                              void* d_out, int out_size)
{
    const float* x      = (const float*)d_in[0];
    const float* W_num  = (const float*)d_in[1];
    const float* b_num  = (const float*)d_in[2];
    const float* W_ih   = (const float*)d_in[3];
    const float* W_hh   = (const float*)d_in[4];
    const float* b_ih   = (const float*)d_in[5];
    const float* b_hh   = (const float*)d_in[6];
    const float* W_aout = (const float*)d_in[7];
    const float* b_aout = (const float*)d_in[8];
    const float* W_fh   = (const float*)d_in[9];
    const float* b_fh   = (const float*)d_in[10];
    const float* W_iouh = (const float*)d_in[11];
    const float* b_iouh = (const float*)d_in[12];
    const float* W_oout = (const float*)d_in[13];
    const float* b_oout = (const float*)d_in[14];

    (void)in_sizes; (void)n_in; (void)out_size;

    cudaFuncSetAttribute(lstm_main, cudaFuncAttributeMaxDynamicSharedMemorySize, SMEM_BYTES);

    lstm_main<<<NBLK, NTH, SMEM_BYTES>>>(x, W_num, b_num, W_ih, W_hh, b_ih, b_hh,
                                         W_aout, b_aout, W_fh, b_fh,
                                         W_iouh, b_iouh, W_oout, b_oout, (float*)d_out);
}